// round 13
// baseline (speedup 1.0000x reference)
#include <cuda_runtime.h>
#include <cstdint>

#define N_NODES 50000
#define N_EDGES 1600000
#define FD 128

// ---------------- scratch (device globals, natively typed) -----------------
__device__ float4   g_agg4[(size_t)N_NODES * 32];  // mean messages (25.6 MB)
__device__ unsigned g_count[N_NODES];              // histogram of destinations
__device__ unsigned g_fill[N_NODES];               // fill cursors
__device__ int      g_rowptr[N_NODES + 1];         // CSR row pointers (by dst)
__device__ int      g_eidx[N_EDGES];               // CSR: source node per slot
__device__ float4   g_Wt4[FD * 32];                // W^T rows as float4 groups
__device__ float4   g_Bt4[FD * 32];                // B^T
__device__ int      g_is64;                        // 1 if edge_index is int64

// ---------------- helpers ----------------
__device__ __forceinline__ int clamp_node(int v) {
    return (v >= 0 && v < N_NODES) ? v : 0;
}

// ---------------- kernel 0: detect edge_index dtype ------------------------
// int64 values < 50000 => every odd 32-bit word is 0. Sample 256 odd words.
__global__ void detect_kernel(const int* __restrict__ ei_words) {
    int lane = threadIdx.x;   // 32 threads
    int nz = 0;
    #pragma unroll
    for (int i = 0; i < 8; i++)
        nz |= ei_words[(lane * 8 + i) * 2 + 1];   // first 512 B: safe either way
    unsigned any = __ballot_sync(0xffffffffu, nz != 0);
    if (lane == 0) g_is64 = (any == 0u) ? 1 : 0;
}

// ---------------- kernel 1: zero counters ----------------
__global__ void zero_kernel() {
    int idx = blockIdx.x * blockDim.x + threadIdx.x;
    int stride = gridDim.x * blockDim.x;
    for (int i = idx; i < N_NODES; i += stride) {
        g_count[i] = 0u;
        g_fill[i] = 0u;
    }
}

// ---------------- kernel 2: histogram destinations -------------------------
__global__ void hist_kernel(const void* __restrict__ ei) {
    const int is64 = g_is64;
    const long long* __restrict__ d64 = (const long long*)ei + N_EDGES;
    const int*       __restrict__ d32 = (const int*)ei + N_EDGES;
    int idx = blockIdx.x * blockDim.x + threadIdx.x;
    int stride = gridDim.x * blockDim.x;
    for (int i = idx; i < N_EDGES; i += stride) {
        int d = is64 ? (int)d64[i] : d32[i];
        atomicAdd(&g_count[clamp_node(d)], 1u);
    }
}

// ---------------- kernel 3: single-WARP scan -> rowptr ----------------------
__global__ void scan_kernel() {
    const int CH = (N_NODES + 31) / 32;   // 1563
    int t = threadIdx.x;                  // 0..31
    int beg = t * CH;
    int end = min(beg + CH, N_NODES);
    int s = 0;
    for (int i = beg; i < end; i++) s += (int)g_count[i];
    int v = s;
    #pragma unroll
    for (int off = 1; off < 32; off <<= 1) {
        int u = __shfl_up_sync(0xffffffffu, v, off);
        if (t >= off) v += u;
    }
    int excl = v - s;
    for (int i = beg; i < end; i++) {
        int c = (int)g_count[i];
        g_rowptr[i] = excl;
        excl += c;
    }
    if (t == 31) g_rowptr[N_NODES] = excl;
}

// ---------------- kernel 4: fill CSR slots ----------------------------------
__global__ void fill_kernel(const void* __restrict__ ei) {
    const int is64 = g_is64;
    const long long* __restrict__ s64 = (const long long*)ei;
    const long long* __restrict__ d64 = (const long long*)ei + N_EDGES;
    const int*       __restrict__ s32 = (const int*)ei;
    const int*       __restrict__ d32 = (const int*)ei + N_EDGES;
    int idx = blockIdx.x * blockDim.x + threadIdx.x;
    int stride = gridDim.x * blockDim.x;
    for (int i = idx; i < N_EDGES; i += stride) {
        int s = is64 ? (int)s64[i] : s32[i];
        int d = is64 ? (int)d64[i] : d32[i];
        d = clamp_node(d);
        int slot = g_rowptr[d] + (int)atomicAdd(&g_fill[d], 1u);
        slot = min(max(slot, 0), N_EDGES - 1);     // belt + braces
        g_eidx[slot] = clamp_node(s);
    }
}

// ---------------- kernel 5: gather + mean (warp per node, no atomics) ------
__global__ __launch_bounds__(256) void gather_kernel(const float4* __restrict__ x4) {
    int warp = (blockIdx.x * blockDim.x + threadIdx.x) >> 5;
    int lane = threadIdx.x & 31;
    if (warp < N_NODES) {
        int start = g_rowptr[warp];
        int end   = g_rowptr[warp + 1];
        float4 acc = make_float4(0.f, 0.f, 0.f, 0.f);

        int base = start;
        for (; base + 32 <= end; base += 32) {
            int eid = g_eidx[base + lane];
            #pragma unroll
            for (int i = 0; i < 32; i++) {
                int si = __shfl_sync(0xffffffffu, eid, i);
                float4 v = x4[(size_t)si * 32 + lane];
                acc.x += v.x; acc.y += v.y; acc.z += v.z; acc.w += v.w;
            }
        }
        int rem = end - base;
        if (rem > 0) {
            int eid = (lane < rem) ? g_eidx[base + lane] : 0;
            for (int i = 0; i < rem; i++) {
                int si = __shfl_sync(0xffffffffu, eid, i);
                float4 v = x4[(size_t)si * 32 + lane];
                acc.x += v.x; acc.y += v.y; acc.z += v.z; acc.w += v.w;
            }
        }

        int deg = end - start;
        float rdeg = 1.0f / (float)(deg > 0 ? deg : 1);
        acc.x *= rdeg; acc.y *= rdeg; acc.z *= rdeg; acc.w *= rdeg;
        g_agg4[(size_t)warp * 32 + lane] = acc;
    }
}

// ---------------- kernel 6: transpose W and B -------------------------------
__global__ void transpose_wb(const float* __restrict__ W, const float* __restrict__ B) {
    int idx = blockIdx.x * blockDim.x + threadIdx.x;   // 0..4095
    if (idx < FD * 32) {
        int k  = idx >> 5;
        int jg = idx & 31;
        int j0 = jg * 4;
        float4 w, b;
        w.x = W[(j0 + 0) * FD + k]; w.y = W[(j0 + 1) * FD + k];
        w.z = W[(j0 + 2) * FD + k]; w.w = W[(j0 + 3) * FD + k];
        b.x = B[(j0 + 0) * FD + k]; b.y = B[(j0 + 1) * FD + k];
        b.z = B[(j0 + 2) * FD + k]; b.w = B[(j0 + 3) * FD + k];
        g_Wt4[k * 32 + jg] = w;
        g_Bt4[k * 32 + jg] = b;
    }
}

// ---------------- kernel 7: update GEMM, shared-memory-free ----------------
__device__ __forceinline__ float4 shfl_f4(float4 v, int srcLane) {
    float4 r;
    r.x = __shfl_sync(0xffffffffu, v.x, srcLane);
    r.y = __shfl_sync(0xffffffffu, v.y, srcLane);
    r.z = __shfl_sync(0xffffffffu, v.z, srcLane);
    r.w = __shfl_sync(0xffffffffu, v.w, srcLane);
    return r;
}

__global__ __launch_bounds__(256) void update_kernel(const float4* __restrict__ x4,
                                                     float* __restrict__ out) {
    int warp = (blockIdx.x * blockDim.x + threadIdx.x) >> 5;
    int lane = threadIdx.x & 31;
    int row0 = warp * 4;
    if (row0 >= N_NODES) return;

    float4 m4[4], xv[4];
    #pragma unroll
    for (int r = 0; r < 4; r++) {
        int gi = row0 + r;
        m4[r] = g_agg4[(size_t)gi * 32 + lane];
        xv[r] = x4[(size_t)gi * 32 + lane];
    }

    float4 acc[4];
    #pragma unroll
    for (int r = 0; r < 4; r++) acc[r] = make_float4(0.f, 0.f, 0.f, 0.f);

    for (int kk = 0; kk < 32; kk++) {
        float4 w0 = g_Wt4[(kk * 4 + 0) * 32 + lane];
        float4 w1 = g_Wt4[(kk * 4 + 1) * 32 + lane];
        float4 w2 = g_Wt4[(kk * 4 + 2) * 32 + lane];
        float4 w3 = g_Wt4[(kk * 4 + 3) * 32 + lane];
        float4 b0 = g_Bt4[(kk * 4 + 0) * 32 + lane];
        float4 b1 = g_Bt4[(kk * 4 + 1) * 32 + lane];
        float4 b2 = g_Bt4[(kk * 4 + 2) * 32 + lane];
        float4 b3 = g_Bt4[(kk * 4 + 3) * 32 + lane];

        #pragma unroll
        for (int r = 0; r < 4; r++) {
            float4 bm = shfl_f4(m4[r], kk);
            float4 bx = shfl_f4(xv[r], kk);
            acc[r].x += bm.x * w0.x + bm.y * w1.x + bm.z * w2.x + bm.w * w3.x
                      + bx.x * b0.x + bx.y * b1.x + bx.z * b2.x + bx.w * b3.x;
            acc[r].y += bm.x * w0.y + bm.y * w1.y + bm.z * w2.y + bm.w * w3.y
                      + bx.x * b0.y + bx.y * b1.y + bx.z * b2.y + bx.w * b3.y;
            acc[r].z += bm.x * w0.z + bm.y * w1.z + bm.z * w2.z + bm.w * w3.z
                      + bx.x * b0.z + bx.y * b1.z + bx.z * b2.z + bx.w * b3.z;
            acc[r].w += bm.x * w0.w + bm.y * w1.w + bm.z * w2.w + bm.w * w3.w
                      + bx.x * b0.w + bx.y * b1.w + bx.z * b2.w + bx.w * b3.w;
        }
    }

    #pragma unroll
    for (int r = 0; r < 4; r++) {
        int gi = row0 + r;
        float* po = out + (size_t)gi * FD + lane * 4;
        po[0] = acc[r].x;
        po[1] = acc[r].y;
        po[2] = acc[r].z;
        po[3] = acc[r].w;
    }
}

// ---------------- launch ----------------
extern "C" void kernel_launch(void* const* d_in, const int* in_sizes, int n_in,
                              void* d_out, int out_size) {
    const float* x  = (const float*)d_in[0];
    const void*  ei = d_in[1];
    const float* W  = (const float*)d_in[2];
    const float* B  = (const float*)d_in[3];
    float*       out = (float*)d_out;

    detect_kernel<<<1, 32>>>((const int*)ei);
    zero_kernel<<<98, 512>>>();
    hist_kernel<<<1536, 256>>>(ei);
    scan_kernel<<<1, 32>>>();
    fill_kernel<<<1536, 256>>>(ei);
    gather_kernel<<<(N_NODES + 7) / 8, 256>>>((const float4*)x);
    transpose_wb<<<16, 256>>>(W, B);
    update_kernel<<<(N_NODES / 4 + 7) / 8, 256>>>((const float4*)x, out);
}

// round 14
// speedup vs baseline: 1.6853x; 1.6853x over previous
#include <cuda_runtime.h>
#include <cstdint>

#define N_NODES 50000
#define N_EDGES 1600000
#define FD 128

// ---------------- scratch (device globals, natively typed) -----------------
__device__ float4   g_agg4[(size_t)N_NODES * 32];  // mean messages (25.6 MB)
__device__ unsigned g_count[N_NODES];              // histogram of destinations
__device__ unsigned g_fill[N_NODES];               // fill cursors
__device__ int      g_rowptr[N_NODES + 1];         // CSR row pointers (by dst)
__device__ int      g_eidx[N_EDGES];               // CSR: source node per slot
__device__ float4   g_Wt4[FD * 32];                // W^T rows as float4 groups
__device__ float4   g_Bt4[FD * 32];                // B^T
__device__ int      g_is64;                        // 1 if edge_index is int64
__device__ int      g_psum[1024];                  // scan partials

#define SC_T  1024
#define SC_CH ((N_NODES + SC_T - 1) / SC_T)        // 49

// ---------------- helpers ----------------
__device__ __forceinline__ int clamp_node(int v) {
    return (v >= 0 && v < N_NODES) ? v : 0;
}

// ---------------- kernel 0: detect edge_index dtype ------------------------
__global__ void detect_kernel(const int* __restrict__ ei_words) {
    int lane = threadIdx.x;   // 32 threads
    int nz = 0;
    #pragma unroll
    for (int i = 0; i < 8; i++)
        nz |= ei_words[(lane * 8 + i) * 2 + 1];
    unsigned any = __ballot_sync(0xffffffffu, nz != 0);
    if (lane == 0) g_is64 = (any == 0u) ? 1 : 0;
}

// ---------------- kernel 1: zero counters ----------------
__global__ void zero_kernel() {
    int idx = blockIdx.x * blockDim.x + threadIdx.x;
    int stride = gridDim.x * blockDim.x;
    for (int i = idx; i < N_NODES; i += stride) {
        g_count[i] = 0u;
        g_fill[i] = 0u;
    }
}

// ---------------- kernel 2: histogram destinations -------------------------
__global__ void hist_kernel(const void* __restrict__ ei) {
    const int is64 = g_is64;
    const long long* __restrict__ d64 = (const long long*)ei + N_EDGES;
    const int*       __restrict__ d32 = (const int*)ei + N_EDGES;
    int idx = blockIdx.x * blockDim.x + threadIdx.x;
    int stride = gridDim.x * blockDim.x;
    for (int i = idx; i < N_EDGES; i += stride) {
        int d = is64 ? (int)d64[i] : d32[i];
        atomicAdd(&g_count[clamp_node(d)], 1u);
    }
}

// ---------------- scan stage 1: per-chunk sums (1024-way parallel) ---------
__global__ void scan1_kernel() {
    int t = blockIdx.x * blockDim.x + threadIdx.x;   // 0..1023
    if (t < SC_T) {
        int beg = t * SC_CH;
        int end = min(beg + SC_CH, N_NODES);
        int s = 0;
        for (int i = beg; i < end; i++) s += (int)g_count[i];
        g_psum[t] = s;
    }
}

// ---------------- scan stage 2: 1 warp scans the 1024 partials -------------
__global__ void scan2_kernel() {
    int lane = threadIdx.x;       // 0..31
    int base = lane * 32;
    int s = 0;
    for (int i = 0; i < 32; i++) s += g_psum[base + i];
    int v = s;
    #pragma unroll
    for (int off = 1; off < 32; off <<= 1) {
        int u = __shfl_up_sync(0xffffffffu, v, off);
        if (lane >= off) v += u;
    }
    int excl = v - s;             // exclusive prefix of this lane's 32 partials
    for (int i = 0; i < 32; i++) {
        int c = g_psum[base + i];
        g_psum[base + i] = excl;  // rewrite as exclusive prefixes
        excl += c;
    }
}

// ---------------- scan stage 3: write rowptr (1024-way parallel) -----------
__global__ void scan3_kernel() {
    int t = blockIdx.x * blockDim.x + threadIdx.x;   // 0..1023
    if (t < SC_T) {
        int beg = t * SC_CH;
        int end = min(beg + SC_CH, N_NODES);
        int excl = g_psum[t];
        for (int i = beg; i < end; i++) {
            int c = (int)g_count[i];
            g_rowptr[i] = excl;
            excl += c;
        }
        if (t == SC_T - 1) g_rowptr[N_NODES] = excl;
    }
}

// ---------------- kernel 4: fill CSR slots ----------------------------------
__global__ void fill_kernel(const void* __restrict__ ei) {
    const int is64 = g_is64;
    const long long* __restrict__ s64 = (const long long*)ei;
    const long long* __restrict__ d64 = (const long long*)ei + N_EDGES;
    const int*       __restrict__ s32 = (const int*)ei;
    const int*       __restrict__ d32 = (const int*)ei + N_EDGES;
    int idx = blockIdx.x * blockDim.x + threadIdx.x;
    int stride = gridDim.x * blockDim.x;
    for (int i = idx; i < N_EDGES; i += stride) {
        int s = is64 ? (int)s64[i] : s32[i];
        int d = is64 ? (int)d64[i] : d32[i];
        d = clamp_node(d);
        int slot = g_rowptr[d] + (int)atomicAdd(&g_fill[d], 1u);
        slot = min(max(slot, 0), N_EDGES - 1);
        g_eidx[slot] = clamp_node(s);
    }
}

// ---------------- kernel 5: gather + mean (warp per node, no atomics) ------
__global__ __launch_bounds__(256) void gather_kernel(const float4* __restrict__ x4) {
    int warp = (blockIdx.x * blockDim.x + threadIdx.x) >> 5;
    int lane = threadIdx.x & 31;
    if (warp < N_NODES) {
        int start = g_rowptr[warp];
        int end   = g_rowptr[warp + 1];
        float4 acc = make_float4(0.f, 0.f, 0.f, 0.f);

        int base = start;
        for (; base + 32 <= end; base += 32) {
            int eid = g_eidx[base + lane];
            #pragma unroll
            for (int i = 0; i < 32; i++) {
                int si = __shfl_sync(0xffffffffu, eid, i);
                float4 v = x4[(size_t)si * 32 + lane];
                acc.x += v.x; acc.y += v.y; acc.z += v.z; acc.w += v.w;
            }
        }
        int rem = end - base;
        if (rem > 0) {
            int eid = (lane < rem) ? g_eidx[base + lane] : 0;
            for (int i = 0; i < rem; i++) {
                int si = __shfl_sync(0xffffffffu, eid, i);
                float4 v = x4[(size_t)si * 32 + lane];
                acc.x += v.x; acc.y += v.y; acc.z += v.z; acc.w += v.w;
            }
        }

        int deg = end - start;
        float rdeg = 1.0f / (float)(deg > 0 ? deg : 1);
        acc.x *= rdeg; acc.y *= rdeg; acc.z *= rdeg; acc.w *= rdeg;
        g_agg4[(size_t)warp * 32 + lane] = acc;
    }
}

// ---------------- kernel 6: transpose W and B -------------------------------
__global__ void transpose_wb(const float* __restrict__ W, const float* __restrict__ B) {
    int idx = blockIdx.x * blockDim.x + threadIdx.x;   // 0..4095
    if (idx < FD * 32) {
        int k  = idx >> 5;
        int jg = idx & 31;
        int j0 = jg * 4;
        float4 w, b;
        w.x = W[(j0 + 0) * FD + k]; w.y = W[(j0 + 1) * FD + k];
        w.z = W[(j0 + 2) * FD + k]; w.w = W[(j0 + 3) * FD + k];
        b.x = B[(j0 + 0) * FD + k]; b.y = B[(j0 + 1) * FD + k];
        b.z = B[(j0 + 2) * FD + k]; b.w = B[(j0 + 3) * FD + k];
        g_Wt4[k * 32 + jg] = w;
        g_Bt4[k * 32 + jg] = b;
    }
}

// ---------------- kernel 7: update GEMM, shared-memory-free ----------------
__device__ __forceinline__ float4 shfl_f4(float4 v, int srcLane) {
    float4 r;
    r.x = __shfl_sync(0xffffffffu, v.x, srcLane);
    r.y = __shfl_sync(0xffffffffu, v.y, srcLane);
    r.z = __shfl_sync(0xffffffffu, v.z, srcLane);
    r.w = __shfl_sync(0xffffffffu, v.w, srcLane);
    return r;
}

__global__ __launch_bounds__(256) void update_kernel(const float4* __restrict__ x4,
                                                     float* __restrict__ out) {
    int warp = (blockIdx.x * blockDim.x + threadIdx.x) >> 5;
    int lane = threadIdx.x & 31;
    int row0 = warp * 4;
    if (row0 >= N_NODES) return;

    float4 m4[4], xv[4];
    #pragma unroll
    for (int r = 0; r < 4; r++) {
        int gi = row0 + r;
        m4[r] = g_agg4[(size_t)gi * 32 + lane];
        xv[r] = x4[(size_t)gi * 32 + lane];
    }

    float4 acc[4];
    #pragma unroll
    for (int r = 0; r < 4; r++) acc[r] = make_float4(0.f, 0.f, 0.f, 0.f);

    for (int kk = 0; kk < 32; kk++) {
        float4 w0 = g_Wt4[(kk * 4 + 0) * 32 + lane];
        float4 w1 = g_Wt4[(kk * 4 + 1) * 32 + lane];
        float4 w2 = g_Wt4[(kk * 4 + 2) * 32 + lane];
        float4 w3 = g_Wt4[(kk * 4 + 3) * 32 + lane];
        float4 b0 = g_Bt4[(kk * 4 + 0) * 32 + lane];
        float4 b1 = g_Bt4[(kk * 4 + 1) * 32 + lane];
        float4 b2 = g_Bt4[(kk * 4 + 2) * 32 + lane];
        float4 b3 = g_Bt4[(kk * 4 + 3) * 32 + lane];

        #pragma unroll
        for (int r = 0; r < 4; r++) {
            float4 bm = shfl_f4(m4[r], kk);
            float4 bx = shfl_f4(xv[r], kk);
            acc[r].x += bm.x * w0.x + bm.y * w1.x + bm.z * w2.x + bm.w * w3.x
                      + bx.x * b0.x + bx.y * b1.x + bx.z * b2.x + bx.w * b3.x;
            acc[r].y += bm.x * w0.y + bm.y * w1.y + bm.z * w2.y + bm.w * w3.y
                      + bx.x * b0.y + bx.y * b1.y + bx.z * b2.y + bx.w * b3.y;
            acc[r].z += bm.x * w0.z + bm.y * w1.z + bm.z * w2.z + bm.w * w3.z
                      + bx.x * b0.z + bx.y * b1.z + bx.z * b2.z + bx.w * b3.z;
            acc[r].w += bm.x * w0.w + bm.y * w1.w + bm.z * w2.w + bm.w * w3.w
                      + bx.x * b0.w + bx.y * b1.w + bx.z * b2.w + bx.w * b3.w;
        }
    }

    #pragma unroll
    for (int r = 0; r < 4; r++) {
        int gi = row0 + r;
        float* po = out + (size_t)gi * FD + lane * 4;
        po[0] = acc[r].x;
        po[1] = acc[r].y;
        po[2] = acc[r].z;
        po[3] = acc[r].w;
    }
}

// ---------------- launch ----------------
extern "C" void kernel_launch(void* const* d_in, const int* in_sizes, int n_in,
                              void* d_out, int out_size) {
    const float* x  = (const float*)d_in[0];
    const void*  ei = d_in[1];
    const float* W  = (const float*)d_in[2];
    const float* B  = (const float*)d_in[3];
    float*       out = (float*)d_out;

    detect_kernel<<<1, 32>>>((const int*)ei);
    zero_kernel<<<98, 512>>>();
    hist_kernel<<<1536, 256>>>(ei);
    scan1_kernel<<<4, 256>>>();
    scan2_kernel<<<1, 32>>>();
    scan3_kernel<<<4, 256>>>();
    fill_kernel<<<1536, 256>>>(ei);
    gather_kernel<<<(N_NODES + 7) / 8, 256>>>((const float4*)x);
    transpose_wb<<<16, 256>>>(W, B);
    update_kernel<<<(N_NODES / 4 + 7) / 8, 256>>>((const float4*)x, out);
}

// round 17
// speedup vs baseline: 1.7859x; 1.0597x over previous
#include <cuda_runtime.h>
#include <cstdint>

#define N_NODES 50000
#define N_EDGES 1600000
#define FD 128

// ---------------- scratch (device globals, natively typed) -----------------
__device__ float4     g_agg4[(size_t)N_NODES * 32]; // mean messages (25.6 MB)
__device__ unsigned   g_count[N_NODES];             // histogram of destinations
__device__ unsigned   g_fill[N_NODES];              // absolute fill cursors
__device__ int        g_rowptr[N_NODES + 1];        // CSR row pointers (by dst)
__device__ int        g_eidx[N_EDGES];              // CSR: source node per slot
__device__ ulonglong2 g_Wt2[FD * 32];               // W^T packed f32x2 pairs
__device__ ulonglong2 g_Bt2[FD * 32];               // B^T packed
__device__ int        g_is64;                       // 1 if edge_index is int64
__device__ int        g_psum[1024];                 // scan partials

#define SC_T  1024
#define SC_CH ((N_NODES + SC_T - 1) / SC_T)         // 49

// ---------------- helpers ----------------
__device__ __forceinline__ int clamp_node(int v) {
    return (v >= 0 && v < N_NODES) ? v : 0;
}
__device__ __forceinline__ unsigned long long pack2(float a, float b) {
    unsigned long long r;
    asm("mov.b64 %0, {%1, %2};" : "=l"(r) : "f"(a), "f"(b));
    return r;
}
__device__ __forceinline__ unsigned long long bcast2(float a) {
    unsigned long long r;
    asm("mov.b64 %0, {%1, %1};" : "=l"(r) : "f"(a));
    return r;
}
__device__ __forceinline__ unsigned long long fma2(unsigned long long a,
                                                   unsigned long long b,
                                                   unsigned long long c) {
    unsigned long long d;
    asm("fma.rn.f32x2 %0, %1, %2, %3;" : "=l"(d) : "l"(a), "l"(b), "l"(c));
    return d;
}
__device__ __forceinline__ float2 unpack2(unsigned long long p) {
    float2 r;
    asm("mov.b64 {%0, %1}, %2;" : "=f"(r.x), "=f"(r.y) : "l"(p));
    return r;
}

// ---------------- kernel 0: detect edge_index dtype ------------------------
__global__ void detect_kernel(const int* __restrict__ ei_words) {
    int lane = threadIdx.x;   // 32 threads
    int nz = 0;
    #pragma unroll
    for (int i = 0; i < 8; i++)
        nz |= ei_words[(lane * 8 + i) * 2 + 1];
    unsigned any = __ballot_sync(0xffffffffu, nz != 0);
    if (lane == 0) g_is64 = (any == 0u) ? 1 : 0;
}

// ---------------- kernel 1: zero histogram ----------------
__global__ void zero_kernel() {
    int idx = blockIdx.x * blockDim.x + threadIdx.x;
    int stride = gridDim.x * blockDim.x;
    for (int i = idx; i < N_NODES; i += stride)
        g_count[i] = 0u;
}

// ---------------- kernel 2: histogram destinations -------------------------
__global__ void hist_kernel(const void* __restrict__ ei) {
    const int is64 = g_is64;
    const long long* __restrict__ d64 = (const long long*)ei + N_EDGES;
    const int*       __restrict__ d32 = (const int*)ei + N_EDGES;
    int idx = blockIdx.x * blockDim.x + threadIdx.x;
    int stride = gridDim.x * blockDim.x;
    for (int i = idx; i < N_EDGES; i += stride) {
        int d = is64 ? (int)d64[i] : d32[i];
        atomicAdd(&g_count[clamp_node(d)], 1u);
    }
}

// ---------------- scan stage 1: per-chunk sums -----------------------------
__global__ void scan1_kernel() {
    int t = blockIdx.x * blockDim.x + threadIdx.x;   // 0..1023
    if (t < SC_T) {
        int beg = t * SC_CH;
        int end = min(beg + SC_CH, N_NODES);
        int s = 0;
        for (int i = beg; i < end; i++) s += (int)g_count[i];
        g_psum[t] = s;
    }
}

// ---------------- scan stage 2: 1 warp scans 1024 partials ------------------
__global__ void scan2_kernel() {
    int lane = threadIdx.x;       // 0..31
    int base = lane * 32;
    int s = 0;
    for (int i = 0; i < 32; i++) s += g_psum[base + i];
    int v = s;
    #pragma unroll
    for (int off = 1; off < 32; off <<= 1) {
        int u = __shfl_up_sync(0xffffffffu, v, off);
        if (lane >= off) v += u;
    }
    int excl = v - s;
    for (int i = 0; i < 32; i++) {
        int c = g_psum[base + i];
        g_psum[base + i] = excl;
        excl += c;
    }
}

// ---------------- scan stage 3: write rowptr + init cursors -----------------
__global__ void scan3_kernel() {
    int t = blockIdx.x * blockDim.x + threadIdx.x;   // 0..1023
    if (t < SC_T) {
        int beg = t * SC_CH;
        int end = min(beg + SC_CH, N_NODES);
        int excl = g_psum[t];
        for (int i = beg; i < end; i++) {
            int c = (int)g_count[i];
            g_rowptr[i] = excl;
            g_fill[i] = (unsigned)excl;   // absolute cursor
            excl += c;
        }
        if (t == SC_T - 1) g_rowptr[N_NODES] = excl;
    }
}

// ---------------- kernel 4: fill CSR slots (absolute cursor) ----------------
__global__ void fill_kernel(const void* __restrict__ ei) {
    const int is64 = g_is64;
    const long long* __restrict__ s64 = (const long long*)ei;
    const long long* __restrict__ d64 = (const long long*)ei + N_EDGES;
    const int*       __restrict__ s32 = (const int*)ei;
    const int*       __restrict__ d32 = (const int*)ei + N_EDGES;
    int idx = blockIdx.x * blockDim.x + threadIdx.x;
    int stride = gridDim.x * blockDim.x;
    for (int i = idx; i < N_EDGES; i += stride) {
        int s = is64 ? (int)s64[i] : s32[i];
        int d = is64 ? (int)d64[i] : d32[i];
        d = clamp_node(d);
        int slot = (int)atomicAdd(&g_fill[d], 1u);   // absolute slot
        slot = min(max(slot, 0), N_EDGES - 1);
        g_eidx[slot] = clamp_node(s);
    }
}

// ---------------- kernel 5: gather + mean (warp per node, no atomics) ------
__global__ __launch_bounds__(256) void gather_kernel(const float4* __restrict__ x4) {
    int warp = (blockIdx.x * blockDim.x + threadIdx.x) >> 5;
    int lane = threadIdx.x & 31;
    if (warp < N_NODES) {
        int start = g_rowptr[warp];
        int end   = g_rowptr[warp + 1];
        float4 acc = make_float4(0.f, 0.f, 0.f, 0.f);

        int base = start;
        for (; base + 32 <= end; base += 32) {
            int eid = g_eidx[base + lane];
            #pragma unroll
            for (int i = 0; i < 32; i++) {
                int si = __shfl_sync(0xffffffffu, eid, i);
                float4 v = x4[(size_t)si * 32 + lane];
                acc.x += v.x; acc.y += v.y; acc.z += v.z; acc.w += v.w;
            }
        }
        int rem = end - base;
        if (rem > 0) {
            int eid = (lane < rem) ? g_eidx[base + lane] : 0;
            for (int i = 0; i < rem; i++) {
                int si = __shfl_sync(0xffffffffu, eid, i);
                float4 v = x4[(size_t)si * 32 + lane];
                acc.x += v.x; acc.y += v.y; acc.z += v.z; acc.w += v.w;
            }
        }

        int deg = end - start;
        float rdeg = 1.0f / (float)(deg > 0 ? deg : 1);
        acc.x *= rdeg; acc.y *= rdeg; acc.z *= rdeg; acc.w *= rdeg;
        g_agg4[(size_t)warp * 32 + lane] = acc;
    }
}

// ---------------- kernel 6: transpose + pack W and B ------------------------
__global__ void transpose_wb(const float* __restrict__ W, const float* __restrict__ B) {
    int idx = blockIdx.x * blockDim.x + threadIdx.x;   // 0..4095
    if (idx < FD * 32) {
        int k  = idx >> 5;        // row of W^T (= col of W)
        int jg = idx & 31;        // 4-col group
        int j0 = jg * 4;
        float wx = W[(j0 + 0) * FD + k], wy = W[(j0 + 1) * FD + k];
        float wz = W[(j0 + 2) * FD + k], ww = W[(j0 + 3) * FD + k];
        float bx = B[(j0 + 0) * FD + k], by = B[(j0 + 1) * FD + k];
        float bz = B[(j0 + 2) * FD + k], bw = B[(j0 + 3) * FD + k];
        ulonglong2 w2, b2;
        w2.x = pack2(wx, wy); w2.y = pack2(wz, ww);
        b2.x = pack2(bx, by); b2.y = pack2(bz, bw);
        g_Wt2[k * 32 + jg] = w2;
        g_Bt2[k * 32 + jg] = b2;
    }
}

// ---------------- kernel 7: update GEMM with packed f32x2 FMA ---------------
// out = mean@W^T + x@B^T. One warp per 4 node-rows; lane owns cols
// [lane*4, lane*4+4) as two f32x2 accumulator pairs per row.
__device__ __forceinline__ float4 shfl_f4(float4 v, int srcLane) {
    float4 r;
    r.x = __shfl_sync(0xffffffffu, v.x, srcLane);
    r.y = __shfl_sync(0xffffffffu, v.y, srcLane);
    r.z = __shfl_sync(0xffffffffu, v.z, srcLane);
    r.w = __shfl_sync(0xffffffffu, v.w, srcLane);
    return r;
}

__global__ __launch_bounds__(256) void update_kernel(const float4* __restrict__ x4,
                                                     float4* __restrict__ out4) {
    int warp = (blockIdx.x * blockDim.x + threadIdx.x) >> 5;
    int lane = threadIdx.x & 31;
    int row0 = warp * 4;
    if (row0 >= N_NODES) return;

    float4 m4[4], xv[4];
    #pragma unroll
    for (int r = 0; r < 4; r++) {
        int gi = row0 + r;
        m4[r] = g_agg4[(size_t)gi * 32 + lane];
        xv[r] = x4[(size_t)gi * 32 + lane];
    }

    unsigned long long accA[4], accB[4];   // cols (0,1) and (2,3) of this lane
    #pragma unroll
    for (int r = 0; r < 4; r++) { accA[r] = 0ull; accB[r] = 0ull; }

    for (int kk = 0; kk < 32; kk++) {
        // weights for k = kk*4 .. kk*4+3, this lane's 4 cols (pair-packed)
        ulonglong2 w0 = g_Wt2[(kk * 4 + 0) * 32 + lane];
        ulonglong2 w1 = g_Wt2[(kk * 4 + 1) * 32 + lane];
        ulonglong2 w2 = g_Wt2[(kk * 4 + 2) * 32 + lane];
        ulonglong2 w3 = g_Wt2[(kk * 4 + 3) * 32 + lane];
        ulonglong2 b0 = g_Bt2[(kk * 4 + 0) * 32 + lane];
        ulonglong2 b1 = g_Bt2[(kk * 4 + 1) * 32 + lane];
        ulonglong2 b2 = g_Bt2[(kk * 4 + 2) * 32 + lane];
        ulonglong2 b3 = g_Bt2[(kk * 4 + 3) * 32 + lane];

        #pragma unroll
        for (int r = 0; r < 4; r++) {
            float4 bm = shfl_f4(m4[r], kk);   // m[row r][kk*4 .. +3]
            float4 bx = shfl_f4(xv[r], kk);   // x[row r][kk*4 .. +3]
            unsigned long long pm0 = bcast2(bm.x), pm1 = bcast2(bm.y);
            unsigned long long pm2 = bcast2(bm.z), pm3 = bcast2(bm.w);
            unsigned long long px0 = bcast2(bx.x), px1 = bcast2(bx.y);
            unsigned long long px2 = bcast2(bx.z), px3 = bcast2(bx.w);

            accA[r] = fma2(pm0, w0.x, accA[r]);
            accA[r] = fma2(pm1, w1.x, accA[r]);
            accA[r] = fma2(pm2, w2.x, accA[r]);
            accA[r] = fma2(pm3, w3.x, accA[r]);
            accA[r] = fma2(px0, b0.x, accA[r]);
            accA[r] = fma2(px1, b1.x, accA[r]);
            accA[r] = fma2(px2, b2.x, accA[r]);
            accA[r] = fma2(px3, b3.x, accA[r]);

            accB[r] = fma2(pm0, w0.y, accB[r]);
            accB[r] = fma2(pm1, w1.y, accB[r]);
            accB[r] = fma2(pm2, w2.y, accB[r]);
            accB[r] = fma2(pm3, w3.y, accB[r]);
            accB[r] = fma2(px0, b0.y, accB[r]);
            accB[r] = fma2(px1, b1.y, accB[r]);
            accB[r] = fma2(px2, b2.y, accB[r]);
            accB[r] = fma2(px3, b3.y, accB[r]);
        }
    }

    #pragma unroll
    for (int r = 0; r < 4; r++) {
        int gi = row0 + r;
        float2 lo = unpack2(accA[r]);
        float2 hi = unpack2(accB[r]);
        out4[(size_t)gi * 32 + lane] = make_float4(lo.x, lo.y, hi.x, hi.y);
    }
}

// ---------------- launch ----------------
extern "C" void kernel_launch(void* const* d_in, const int* in_sizes, int n_in,
                              void* d_out, int out_size) {
    const float* x  = (const float*)d_in[0];
    const void*  ei = d_in[1];
    const float* W  = (const float*)d_in[2];
    const float* B  = (const float*)d_in[3];
    float4*      out4 = (float4*)d_out;

    detect_kernel<<<1, 32>>>((const int*)ei);
    zero_kernel<<<98, 512>>>();
    hist_kernel<<<1536, 256>>>(ei);
    scan1_kernel<<<4, 256>>>();
    scan2_kernel<<<1, 32>>>();
    scan3_kernel<<<4, 256>>>();
    fill_kernel<<<1536, 256>>>(ei);
    gather_kernel<<<(N_NODES + 7) / 8, 256>>>((const float4*)x);
    transpose_wb<<<16, 256>>>(W, B);
    update_kernel<<<(N_NODES / 4 + 7) / 8, 256>>>((const float4*)x, out4);
}